// round 3
// baseline (speedup 1.0000x reference)
#include <cuda_runtime.h>
#include <stdint.h>

#define NSAMP 150
#define D_IN  784
#define D_H   512
#define D_OUT 10
#define BATCH 64
#define TILE_N 256

// ---------------- device scratch: activations only ----------------
__device__ __align__(16) float g_H1[NSAMP * BATCH * D_H];
__device__ __align__(16) float g_H2[NSAMP * BATCH * D_H];
__device__ __align__(16) float g_H3[NSAMP * BATCH * D_H];

// ---------------- packed f32x2 helpers ----------------
__device__ __forceinline__ unsigned long long splat_f32x2(float f) {
    unsigned long long r;
    unsigned u = __float_as_uint(f);
    asm("mov.b64 %0, {%1, %2};" : "=l"(r) : "r"(u), "r"(u));
    return r;
}
__device__ __forceinline__ void fma_f32x2(unsigned long long& d,
                                          unsigned long long a,
                                          unsigned long long b) {
    asm("fma.rn.f32x2 %0, %1, %2, %0;" : "+l"(d) : "l"(a), "l"(b));
}
__device__ __forceinline__ void unpack_f32x2(float& lo, float& hi, unsigned long long v) {
    unsigned a, b;
    asm("mov.b64 {%0, %1}, %2;" : "=r"(a), "=r"(b) : "l"(v));
    lo = __uint_as_float(a); hi = __uint_as_float(b);
}

// ---------------- threefry2x32 (20 rounds), bit-exact vs jax._src.prng ----------------
__device__ __forceinline__ void tf_round(uint32_t& x0, uint32_t& x1, int r) {
    x0 += x1;
    x1 = __funnelshift_l(x1, x1, r);
    x1 ^= x0;
}
__device__ __forceinline__ uint2 threefry2x32_dev(uint32_t k0, uint32_t k1,
                                                  uint32_t x0, uint32_t x1) {
    uint32_t k2 = k0 ^ k1 ^ 0x1BD11BDAu;
    x0 += k0; x1 += k1;
    tf_round(x0,x1,13); tf_round(x0,x1,15); tf_round(x0,x1,26); tf_round(x0,x1,6);
    x0 += k1; x1 += k2 + 1u;
    tf_round(x0,x1,17); tf_round(x0,x1,29); tf_round(x0,x1,16); tf_round(x0,x1,24);
    x0 += k2; x1 += k0 + 2u;
    tf_round(x0,x1,13); tf_round(x0,x1,15); tf_round(x0,x1,26); tf_round(x0,x1,6);
    x0 += k0; x1 += k1 + 3u;
    tf_round(x0,x1,17); tf_round(x0,x1,29); tf_round(x0,x1,16); tf_round(x0,x1,24);
    x0 += k1; x1 += k2 + 4u;
    tf_round(x0,x1,13); tf_round(x0,x1,15); tf_round(x0,x1,26); tf_round(x0,x1,6);
    x0 += k2; x1 += k0 + 5u;
    return make_uint2(x0, x1);
}

// ---------------- bits -> N(0,1): fast-math clone of XLA pipeline ----------------
__device__ __forceinline__ float jax_normal_fast(uint32_t bits) {
    const float LO = -0.99999994039535522461f;
    float f = __uint_as_float((bits >> 9) | 0x3f800000u) - 1.0f;
    float x = fmaxf(__fmaf_rn(f, 2.0f, LO), LO);
    float y = x * x;
    float t = 1.0f - y;
    float w;
    if (t == 1.0f) w = y;
    else           w = y * __fdividef(__logf(t), t - 1.0f);
    float p;
    if (w < 5.0f) {
        float ww = w - 2.5f;
        p =                2.81022636e-08f;
        p = __fmaf_rn(p, ww, 3.43273939e-07f);
        p = __fmaf_rn(p, ww, -3.5233877e-06f);
        p = __fmaf_rn(p, ww, -4.39150654e-06f);
        p = __fmaf_rn(p, ww, 0.00021858087f);
        p = __fmaf_rn(p, ww, -0.00125372503f);
        p = __fmaf_rn(p, ww, -0.00417768164f);
        p = __fmaf_rn(p, ww, 0.246640727f);
        p = __fmaf_rn(p, ww, 1.50140941f);
    } else {
        float ww = __fsqrt_rn(w) - 3.0f;
        p =                -0.000200214257f;
        p = __fmaf_rn(p, ww, 0.000100950558f);
        p = __fmaf_rn(p, ww, 0.00134934322f);
        p = __fmaf_rn(p, ww, -0.00367342844f);
        p = __fmaf_rn(p, ww, 0.00573950773f);
        p = __fmaf_rn(p, ww, -0.0076224613f);
        p = __fmaf_rn(p, ww, 0.00943887047f);
        p = __fmaf_rn(p, ww, 1.00167406f);
        p = __fmaf_rn(p, ww, 2.83297682f);
    }
    return 1.4142135623730951f * (p * x);
}

// ---------------- fused: gen W,b on the fly + 64x256 tile GEMM + bias + relu ----------------
// C[s, 0:64, nblk*256..+256] = A[s] @ W[s]^T + b[s]; W[s][n][k] = mu + exp(v)*eps
__global__ __launch_bounds__(256, 2) void fused_layer(
    const float* __restrict__ A, long long strideA,
    const float* __restrict__ muW, const float* __restrict__ vW,
    const float* __restrict__ mub, const float* __restrict__ vb,
    float* __restrict__ C, int K, int N, int relu,
    uint32_t wk0, uint32_t wk1, uint32_t bk0, uint32_t bk1)
{
    const int s    = blockIdx.y;
    const int nblk = blockIdx.x;
    const int t    = threadIdx.x;      // 256

    __shared__ float As[16][68];       // [k][m], 68 pad keeps 16B align + low conflicts
    __shared__ float Bs[16][260];      // [k][n]
    __shared__ float bias_s[TILE_N];

    // ---- index sets ----
    const int gk  = t & 15;            // gen: k within chunk (lanes span k -> coalesced LDG)
    const int gn0 = t >> 4;            // gen: n base 0..15 (stride 16 over i)
    const int ar  = t >> 2;            // A-load: row 0..63
    const int ak  = (t & 3) << 2;      // A-load: k offset 0,4,8,12
    const int tx  = t & 31;            // compute: n-group
    const int ty  = t >> 5;            // compute: m-group (== warp id -> As broadcast)

    const float* Ab = A + (long long)s * strideA;

    // ---- bias for this n-tile ----
    {
        int nb = nblk * TILE_N + t;
        uint2 r = threefry2x32_dev(bk0, bk1, 0u, (uint32_t)(s * N + nb));
        bias_s[t] = __fmaf_rn(__expf(vb[nb]), jax_normal_fast(r.x ^ r.y), mub[nb]);
    }

    // acc pairs along m: acc2[mp][nj]; mp: (ty*4 + 2*p) & half 0/32; nj: tx*4+j & half 0/128
    unsigned long long acc2[4][8];
#pragma unroll
    for (int i = 0; i < 4; i++)
#pragma unroll
        for (int j = 0; j < 8; j++) acc2[i][j] = 0ull;

    for (int k0 = 0; k0 < K; k0 += 16) {
        float4 av = *(const float4*)(Ab + (long long)ar * K + k0 + ak);

        __syncthreads();
        As[ak+0][ar] = av.x; As[ak+1][ar] = av.y; As[ak+2][ar] = av.z; As[ak+3][ar] = av.w;

        // generate 16 weights (one per n-stripe), store straight to smem
#pragma unroll 4
        for (int i = 0; i < 16; i++) {
            int n_loc  = gn0 + 16 * i;
            int n_glob = nblk * TILE_N + n_loc;
            long long off = (long long)n_glob * K + k0 + gk;
            float mu = muW[off];
            float vv = vW[off];
            uint32_t e = (uint32_t)((s * N + n_glob) * K + k0 + gk);
            uint2 r = threefry2x32_dev(wk0, wk1, 0u, e);
            Bs[gk][n_loc] = __fmaf_rn(__expf(vv), jax_normal_fast(r.x ^ r.y), mu);
        }
        __syncthreads();

#pragma unroll
        for (int kk = 0; kk < 16; kk++) {
            union { float4 f; unsigned long long u[2]; } a0, a1, b0, b1;
            a0.f = *(const float4*)&As[kk][ty * 4];
            a1.f = *(const float4*)&As[kk][32 + ty * 4];
            b0.f = *(const float4*)&Bs[kk][tx * 4];
            b1.f = *(const float4*)&Bs[kk][128 + tx * 4];
            float bb[8] = { b0.f.x, b0.f.y, b0.f.z, b0.f.w,
                            b1.f.x, b1.f.y, b1.f.z, b1.f.w };
#pragma unroll
            for (int nj = 0; nj < 8; nj++) {
                unsigned long long bs = splat_f32x2(bb[nj]);
                fma_f32x2(acc2[0][nj], a0.u[0], bs);
                fma_f32x2(acc2[1][nj], a0.u[1], bs);
                fma_f32x2(acc2[2][nj], a1.u[0], bs);
                fma_f32x2(acc2[3][nj], a1.u[1], bs);
            }
        }
    }

    // ---- epilogue: unpack, +bias, relu, store ----
    float4 bv0 = *(const float4*)&bias_s[tx * 4];
    float4 bv1 = *(const float4*)&bias_s[128 + tx * 4];
    const float bb0[8] = { bv0.x, bv0.y, bv0.z, bv0.w, bv1.x, bv1.y, bv1.z, bv1.w };

#pragma unroll
    for (int mp = 0; mp < 4; mp++) {
        int m = ty * 4 + (mp & 1) * 2 + (mp >> 1) * 32;   // rows m, m+1
        float r0[8], r1[8];
#pragma unroll
        for (int nj = 0; nj < 8; nj++) unpack_f32x2(r0[nj], r1[nj], acc2[mp][nj]);
        float* Crow0 = C + ((long long)s * 64 + m    ) * N + nblk * TILE_N;
        float* Crow1 = C + ((long long)s * 64 + m + 1) * N + nblk * TILE_N;
        float4 o;
        if (relu) {
            o = make_float4(fmaxf(r0[0]+bb0[0],0.f), fmaxf(r0[1]+bb0[1],0.f),
                            fmaxf(r0[2]+bb0[2],0.f), fmaxf(r0[3]+bb0[3],0.f));
            *(float4*)&Crow0[tx*4] = o;
            o = make_float4(fmaxf(r0[4]+bb0[4],0.f), fmaxf(r0[5]+bb0[5],0.f),
                            fmaxf(r0[6]+bb0[6],0.f), fmaxf(r0[7]+bb0[7],0.f));
            *(float4*)&Crow0[128 + tx*4] = o;
            o = make_float4(fmaxf(r1[0]+bb0[0],0.f), fmaxf(r1[1]+bb0[1],0.f),
                            fmaxf(r1[2]+bb0[2],0.f), fmaxf(r1[3]+bb0[3],0.f));
            *(float4*)&Crow1[tx*4] = o;
            o = make_float4(fmaxf(r1[4]+bb0[4],0.f), fmaxf(r1[5]+bb0[5],0.f),
                            fmaxf(r1[6]+bb0[6],0.f), fmaxf(r1[7]+bb0[7],0.f));
            *(float4*)&Crow1[128 + tx*4] = o;
        } else {
            o = make_float4(r0[0]+bb0[0], r0[1]+bb0[1], r0[2]+bb0[2], r0[3]+bb0[3]);
            *(float4*)&Crow0[tx*4] = o;
            o = make_float4(r0[4]+bb0[4], r0[5]+bb0[5], r0[6]+bb0[6], r0[7]+bb0[7]);
            *(float4*)&Crow0[128 + tx*4] = o;
            o = make_float4(r1[0]+bb0[0], r1[1]+bb0[1], r1[2]+bb0[2], r1[3]+bb0[3]);
            *(float4*)&Crow1[tx*4] = o;
            o = make_float4(r1[4]+bb0[4], r1[5]+bb0[5], r1[6]+bb0[6], r1[7]+bb0[7]);
            *(float4*)&Crow1[128 + tx*4] = o;
        }
    }
}

// ---------------- final layer: gen W3/b3 into smem, warp-per-row dots ----------------
__global__ __launch_bounds__(256) void layer3_fused(
    const float* __restrict__ H,
    const float* __restrict__ muW, const float* __restrict__ vW,
    const float* __restrict__ mub, const float* __restrict__ vb,
    float* __restrict__ out,
    uint32_t wk0, uint32_t wk1, uint32_t bk0, uint32_t bk1)
{
    const int s = blockIdx.x;
    const int t = threadIdx.x;
    __shared__ float Ws[D_OUT * D_H];
    __shared__ float bsm[D_OUT];

    // generate W3[s] into smem (256 threads x 20 elems), coalesced mu/v reads
#pragma unroll 4
    for (int i = 0; i < (D_OUT * D_H) / 256; i++) {
        int j = t + 256 * i;
        uint32_t e = (uint32_t)(s * (D_OUT * D_H) + j);
        uint2 r = threefry2x32_dev(wk0, wk1, 0u, e);
        Ws[j] = __fmaf_rn(__expf(vW[j]), jax_normal_fast(r.x ^ r.y), muW[j]);
    }
    if (t < D_OUT) {
        uint2 r = threefry2x32_dev(bk0, bk1, 0u, (uint32_t)(s * D_OUT + t));
        bsm[t] = __fmaf_rn(__expf(vb[t]), jax_normal_fast(r.x ^ r.y), mub[t]);
    }
    __syncthreads();

    const int w = t >> 5, l = t & 31;
    const int b0 = blockIdx.y * 32 + w * 4;          // 4 batch rows per warp
#pragma unroll
    for (int ri = 0; ri < 4; ri++) {
        int b = b0 + ri;
        const float* Hb = H + ((long long)s * BATCH + b) * D_H;
        float h[16];
#pragma unroll
        for (int i = 0; i < 16; i++) h[i] = Hb[l + 32 * i];   // coalesced
#pragma unroll
        for (int o = 0; o < D_OUT; o++) {
            float acc = 0.0f;
#pragma unroll
            for (int i = 0; i < 16; i++)
                acc = __fmaf_rn(h[i], Ws[o * D_H + l + 32 * i], acc);  // bank = lane
            acc += __shfl_xor_sync(0xffffffffu, acc, 16);
            acc += __shfl_xor_sync(0xffffffffu, acc, 8);
            acc += __shfl_xor_sync(0xffffffffu, acc, 4);
            acc += __shfl_xor_sync(0xffffffffu, acc, 2);
            acc += __shfl_xor_sync(0xffffffffu, acc, 1);
            if (l == 0) out[((long long)s * BATCH + b) * D_OUT + o] = acc + bsm[o];
        }
    }
}

// ---------------- host-side threefry (subkey derivation) ----------------
static inline uint32_t h_rotl(uint32_t x, int r) { return (x << r) | (x >> (32 - r)); }
static void tf_host(uint32_t k0, uint32_t k1, uint32_t x0, uint32_t x1,
                    uint32_t* o0, uint32_t* o1) {
    uint32_t k2 = k0 ^ k1 ^ 0x1BD11BDAu;
    x0 += k0; x1 += k1;
    static const int R[2][4] = {{13,15,26,6},{17,29,16,24}};
    const uint32_t ks[3] = {k0, k1, k2};
    for (int i = 0; i < 5; i++) {
        for (int r = 0; r < 4; r++) {
            x0 += x1; x1 = h_rotl(x1, R[i & 1][r]); x1 ^= x0;
        }
        x0 += ks[(i + 1) % 3];
        x1 += ks[(i + 2) % 3] + (uint32_t)(i + 1);
    }
    *o0 = x0; *o1 = x1;
}

extern "C" void kernel_launch(void* const* d_in, const int* in_sizes, int n_in,
                              void* d_out, int out_size) {
    const float* x    = (const float*)d_in[0];
    const float* muW0 = (const float*)d_in[1];
    const float* mub0 = (const float*)d_in[2];
    const float* muW1 = (const float*)d_in[3];
    const float* mub1 = (const float*)d_in[4];
    const float* muW2 = (const float*)d_in[5];
    const float* mub2 = (const float*)d_in[6];
    const float* muW3 = (const float*)d_in[7];
    const float* mub3 = (const float*)d_in[8];
    const float* vW0  = (const float*)d_in[9];
    const float* vb0  = (const float*)d_in[10];
    const float* vW1  = (const float*)d_in[11];
    const float* vb1  = (const float*)d_in[12];
    const float* vW2  = (const float*)d_in[13];
    const float* vb2  = (const float*)d_in[14];
    const float* vW3  = (const float*)d_in[15];
    const float* vb3  = (const float*)d_in[16];
    float* out = (float*)d_out;

    uint32_t kk[8][2];
    for (int i = 0; i < 8; i++) tf_host(0u, 1u, 0u, (uint32_t)i, &kk[i][0], &kk[i][1]);

    float *pH1, *pH2, *pH3;
    cudaGetSymbolAddress((void**)&pH1, g_H1);
    cudaGetSymbolAddress((void**)&pH2, g_H2);
    cudaGetSymbolAddress((void**)&pH3, g_H3);

    fused_layer<<<dim3(D_H/TILE_N, NSAMP), 256>>>(x,   0,                    muW0, vW0, mub0, vb0,
                                                  pH1, D_IN, D_H, 1,
                                                  kk[0][0], kk[0][1], kk[1][0], kk[1][1]);
    fused_layer<<<dim3(D_H/TILE_N, NSAMP), 256>>>(pH1, (long long)BATCH*D_H, muW1, vW1, mub1, vb1,
                                                  pH2, D_H, D_H, 1,
                                                  kk[2][0], kk[2][1], kk[3][0], kk[3][1]);
    fused_layer<<<dim3(D_H/TILE_N, NSAMP), 256>>>(pH2, (long long)BATCH*D_H, muW2, vW2, mub2, vb2,
                                                  pH3, D_H, D_H, 1,
                                                  kk[4][0], kk[4][1], kk[5][0], kk[5][1]);
    layer3_fused<<<dim3(NSAMP, 2), 256>>>(pH3, muW3, vW3, mub3, vb3, out,
                                          kk[6][0], kk[6][1], kk[7][0], kk[7][1]);
}

// round 4
// speedup vs baseline: 1.1374x; 1.1374x over previous
#include <cuda_runtime.h>
#include <stdint.h>

#define NSAMP 150
#define D_IN  784
#define D_H   512
#define D_OUT 10
#define BATCH 64

// ---------------- device scratch: activations only ----------------
__device__ __align__(16) float g_H1[NSAMP * BATCH * D_H];
__device__ __align__(16) float g_H2[NSAMP * BATCH * D_H];
__device__ __align__(16) float g_H3[NSAMP * BATCH * D_H];

// ---------------- packed f32x2 helpers ----------------
__device__ __forceinline__ unsigned long long splat_f32x2(float f) {
    unsigned long long r;
    unsigned u = __float_as_uint(f);
    asm("mov.b64 %0, {%1, %2};" : "=l"(r) : "r"(u), "r"(u));
    return r;
}
__device__ __forceinline__ void fma_f32x2(unsigned long long& d,
                                          unsigned long long a,
                                          unsigned long long b) {
    asm("fma.rn.f32x2 %0, %1, %2, %0;" : "+l"(d) : "l"(a), "l"(b));
}
__device__ __forceinline__ void unpack_f32x2(float& lo, float& hi, unsigned long long v) {
    unsigned a, b;
    asm("mov.b64 {%0, %1}, %2;" : "=r"(a), "=r"(b) : "l"(v));
    lo = __uint_as_float(a); hi = __uint_as_float(b);
}

// ---------------- threefry2x32 (20 rounds), bit-exact vs jax._src.prng ----------------
__device__ __forceinline__ void tf_round(uint32_t& x0, uint32_t& x1, int r) {
    x0 += x1;
    x1 = __funnelshift_l(x1, x1, r);
    x1 ^= x0;
}
__device__ __forceinline__ uint2 threefry2x32_dev(uint32_t k0, uint32_t k1,
                                                  uint32_t x0, uint32_t x1) {
    uint32_t k2 = k0 ^ k1 ^ 0x1BD11BDAu;
    x0 += k0; x1 += k1;
    tf_round(x0,x1,13); tf_round(x0,x1,15); tf_round(x0,x1,26); tf_round(x0,x1,6);
    x0 += k1; x1 += k2 + 1u;
    tf_round(x0,x1,17); tf_round(x0,x1,29); tf_round(x0,x1,16); tf_round(x0,x1,24);
    x0 += k2; x1 += k0 + 2u;
    tf_round(x0,x1,13); tf_round(x0,x1,15); tf_round(x0,x1,26); tf_round(x0,x1,6);
    x0 += k0; x1 += k1 + 3u;
    tf_round(x0,x1,17); tf_round(x0,x1,29); tf_round(x0,x1,16); tf_round(x0,x1,24);
    x0 += k1; x1 += k2 + 4u;
    tf_round(x0,x1,13); tf_round(x0,x1,15); tf_round(x0,x1,26); tf_round(x0,x1,6);
    x0 += k2; x1 += k0 + 5u;
    return make_uint2(x0, x1);
}

// ---------------- bits -> N(0,1): fast-math clone of XLA pipeline ----------------
__device__ __forceinline__ float jax_normal_fast(uint32_t bits) {
    const float LO = -0.99999994039535522461f;
    float f = __uint_as_float((bits >> 9) | 0x3f800000u) - 1.0f;
    float x = fmaxf(__fmaf_rn(f, 2.0f, LO), LO);
    float y = x * x;
    float t = 1.0f - y;
    float w;
    if (t == 1.0f) w = y;
    else           w = y * __fdividef(__logf(t), t - 1.0f);
    float p;
    if (w < 5.0f) {
        float ww = w - 2.5f;
        p =                2.81022636e-08f;
        p = __fmaf_rn(p, ww, 3.43273939e-07f);
        p = __fmaf_rn(p, ww, -3.5233877e-06f);
        p = __fmaf_rn(p, ww, -4.39150654e-06f);
        p = __fmaf_rn(p, ww, 0.00021858087f);
        p = __fmaf_rn(p, ww, -0.00125372503f);
        p = __fmaf_rn(p, ww, -0.00417768164f);
        p = __fmaf_rn(p, ww, 0.246640727f);
        p = __fmaf_rn(p, ww, 1.50140941f);
    } else {
        float ww = __fsqrt_rn(w) - 3.0f;
        p =                -0.000200214257f;
        p = __fmaf_rn(p, ww, 0.000100950558f);
        p = __fmaf_rn(p, ww, 0.00134934322f);
        p = __fmaf_rn(p, ww, -0.00367342844f);
        p = __fmaf_rn(p, ww, 0.00573950773f);
        p = __fmaf_rn(p, ww, -0.0076224613f);
        p = __fmaf_rn(p, ww, 0.00943887047f);
        p = __fmaf_rn(p, ww, 1.00167406f);
        p = __fmaf_rn(p, ww, 2.83297682f);
    }
    return 1.4142135623730951f * (p * x);
}

// ---------------- fused layer: 64x64 tile, double-buffered, pipelined gen ----------------
// C[s, 0:64, nblk*64..+64] = relu(A[s] @ W[s]^T + b[s])
__global__ __launch_bounds__(256, 2) void fused_layer(
    const float* __restrict__ A, long long strideA,
    const float* __restrict__ muW, const float* __restrict__ vW,
    const float* __restrict__ mub, const float* __restrict__ vb,
    float* __restrict__ C, int K, int N, int relu,
    uint32_t wk0, uint32_t wk1, uint32_t bk0, uint32_t bk1)
{
    const int s    = blockIdx.y;
    const int nblk = blockIdx.x;
    const int t    = threadIdx.x;      // 256

    __shared__ float As[2][16][68];
    __shared__ float Bs[2][16][68];
    __shared__ float bias_s[64];

    const int lr  = t >> 2;            // 0..63 row (A-row / W-row)
    const int lk4 = (t & 3) << 2;      // k offset 0,4,8,12
    const int tx  = t & 15;            // compute: n-group
    const int ty  = t >> 4;            // compute: m-group

    const float* Ab     = A + (long long)s * strideA;
    const int    n_glob = nblk * 64 + lr;
    const float* muRow  = muW + (long long)n_glob * K;
    const float* vRow   = vW  + (long long)n_glob * K;
    const uint32_t eBase = ((uint32_t)s * (uint32_t)N + (uint32_t)n_glob) * (uint32_t)K;

    if (t < 64) {
        int nb = nblk * 64 + t;
        uint2 r = threefry2x32_dev(bk0, bk1, 0u, (uint32_t)(s * N + nb));
        bias_s[t] = __fmaf_rn(__expf(vb[nb]), jax_normal_fast(r.x ^ r.y), mub[nb]);
    }

    // ---- prologue: load + gen chunk 0 into registers ----
    float4 av = *(const float4*)(Ab + (long long)lr * K + lk4);
    float4 mv = *(const float4*)(muRow + lk4);
    float4 vv = *(const float4*)(vRow  + lk4);
    float w0, w1, w2, w3;
    {
        uint32_t e0 = eBase + lk4;
        uint2 r0 = threefry2x32_dev(wk0, wk1, 0u, e0 + 0);
        uint2 r1 = threefry2x32_dev(wk0, wk1, 0u, e0 + 1);
        uint2 r2 = threefry2x32_dev(wk0, wk1, 0u, e0 + 2);
        uint2 r3 = threefry2x32_dev(wk0, wk1, 0u, e0 + 3);
        w0 = __fmaf_rn(__expf(vv.x), jax_normal_fast(r0.x ^ r0.y), mv.x);
        w1 = __fmaf_rn(__expf(vv.y), jax_normal_fast(r1.x ^ r1.y), mv.y);
        w2 = __fmaf_rn(__expf(vv.z), jax_normal_fast(r2.x ^ r2.y), mv.z);
        w3 = __fmaf_rn(__expf(vv.w), jax_normal_fast(r3.x ^ r3.y), mv.w);
    }

    unsigned long long acc2[2][4];
#pragma unroll
    for (int i = 0; i < 2; i++)
#pragma unroll
        for (int j = 0; j < 4; j++) acc2[i][j] = 0ull;

    const int nch = K >> 4;

    // ---- main loop (all but last chunk): store(c) | sync | gen(c+1) + FMA(c) ----
    for (int c = 0; c < nch - 1; c++) {
        const int buf = c & 1;
        As[buf][lk4+0][lr] = av.x; As[buf][lk4+1][lr] = av.y;
        As[buf][lk4+2][lr] = av.z; As[buf][lk4+3][lr] = av.w;
        Bs[buf][lk4+0][lr] = w0;   Bs[buf][lk4+1][lr] = w1;
        Bs[buf][lk4+2][lr] = w2;   Bs[buf][lk4+3][lr] = w3;
        __syncthreads();

        // load + gen next chunk (ALU-pipe work; interleaves with FMA loop below)
        const int k0n = (c + 1) << 4;
        av = *(const float4*)(Ab + (long long)lr * K + k0n + lk4);
        mv = *(const float4*)(muRow + k0n + lk4);
        vv = *(const float4*)(vRow  + k0n + lk4);
        uint32_t e0 = eBase + (uint32_t)(k0n + lk4);
        uint2 r0 = threefry2x32_dev(wk0, wk1, 0u, e0 + 0);
        uint2 r1 = threefry2x32_dev(wk0, wk1, 0u, e0 + 1);
        uint2 r2 = threefry2x32_dev(wk0, wk1, 0u, e0 + 2);
        uint2 r3 = threefry2x32_dev(wk0, wk1, 0u, e0 + 3);
        w0 = __fmaf_rn(__expf(vv.x), jax_normal_fast(r0.x ^ r0.y), mv.x);
        w1 = __fmaf_rn(__expf(vv.y), jax_normal_fast(r1.x ^ r1.y), mv.y);
        w2 = __fmaf_rn(__expf(vv.z), jax_normal_fast(r2.x ^ r2.y), mv.z);
        w3 = __fmaf_rn(__expf(vv.w), jax_normal_fast(r3.x ^ r3.y), mv.w);

        // FMA over chunk c (FMA pipe + LDS)
#pragma unroll
        for (int kk = 0; kk < 16; kk++) {
            union { float4 f; unsigned long long u[2]; } a, b;
            a.f = *(const float4*)&As[buf][kk][ty * 4];
            b.f = *(const float4*)&Bs[buf][kk][tx * 4];
            unsigned long long s0 = splat_f32x2(b.f.x);
            unsigned long long s1 = splat_f32x2(b.f.y);
            unsigned long long s2 = splat_f32x2(b.f.z);
            unsigned long long s3 = splat_f32x2(b.f.w);
            fma_f32x2(acc2[0][0], a.u[0], s0);
            fma_f32x2(acc2[0][1], a.u[0], s1);
            fma_f32x2(acc2[0][2], a.u[0], s2);
            fma_f32x2(acc2[0][3], a.u[0], s3);
            fma_f32x2(acc2[1][0], a.u[1], s0);
            fma_f32x2(acc2[1][1], a.u[1], s1);
            fma_f32x2(acc2[1][2], a.u[1], s2);
            fma_f32x2(acc2[1][3], a.u[1], s3);
        }
    }

    // ---- last chunk: store + FMA only ----
    {
        const int buf = (nch - 1) & 1;
        As[buf][lk4+0][lr] = av.x; As[buf][lk4+1][lr] = av.y;
        As[buf][lk4+2][lr] = av.z; As[buf][lk4+3][lr] = av.w;
        Bs[buf][lk4+0][lr] = w0;   Bs[buf][lk4+1][lr] = w1;
        Bs[buf][lk4+2][lr] = w2;   Bs[buf][lk4+3][lr] = w3;
        __syncthreads();
#pragma unroll
        for (int kk = 0; kk < 16; kk++) {
            union { float4 f; unsigned long long u[2]; } a, b;
            a.f = *(const float4*)&As[buf][kk][ty * 4];
            b.f = *(const float4*)&Bs[buf][kk][tx * 4];
            unsigned long long s0 = splat_f32x2(b.f.x);
            unsigned long long s1 = splat_f32x2(b.f.y);
            unsigned long long s2 = splat_f32x2(b.f.z);
            unsigned long long s3 = splat_f32x2(b.f.w);
            fma_f32x2(acc2[0][0], a.u[0], s0);
            fma_f32x2(acc2[0][1], a.u[0], s1);
            fma_f32x2(acc2[0][2], a.u[0], s2);
            fma_f32x2(acc2[0][3], a.u[0], s3);
            fma_f32x2(acc2[1][0], a.u[1], s0);
            fma_f32x2(acc2[1][1], a.u[1], s1);
            fma_f32x2(acc2[1][2], a.u[1], s2);
            fma_f32x2(acc2[1][3], a.u[1], s3);
        }
    }

    // ---- epilogue ----
    float4 bv = *(const float4*)&bias_s[tx * 4];
    const float bb[4] = { bv.x, bv.y, bv.z, bv.w };
#pragma unroll
    for (int p = 0; p < 2; p++) {
        float r0[4], r1[4];
#pragma unroll
        for (int nj = 0; nj < 4; nj++) unpack_f32x2(r0[nj], r1[nj], acc2[p][nj]);
        int m = ty * 4 + 2 * p;
        float* Crow0 = C + ((long long)s * 64 + m    ) * N + nblk * 64;
        float* Crow1 = C + ((long long)s * 64 + m + 1) * N + nblk * 64;
        float4 o0, o1;
        if (relu) {
            o0 = make_float4(fmaxf(r0[0]+bb[0],0.f), fmaxf(r0[1]+bb[1],0.f),
                             fmaxf(r0[2]+bb[2],0.f), fmaxf(r0[3]+bb[3],0.f));
            o1 = make_float4(fmaxf(r1[0]+bb[0],0.f), fmaxf(r1[1]+bb[1],0.f),
                             fmaxf(r1[2]+bb[2],0.f), fmaxf(r1[3]+bb[3],0.f));
        } else {
            o0 = make_float4(r0[0]+bb[0], r0[1]+bb[1], r0[2]+bb[2], r0[3]+bb[3]);
            o1 = make_float4(r1[0]+bb[0], r1[1]+bb[1], r1[2]+bb[2], r1[3]+bb[3]);
        }
        *(float4*)&Crow0[tx * 4] = o0;
        *(float4*)&Crow1[tx * 4] = o1;
    }
}

// ---------------- final layer: one block per sample; warp-per-8-rows dots ----------------
__global__ __launch_bounds__(256) void layer3_fused(
    const float* __restrict__ H,
    const float* __restrict__ muW, const float* __restrict__ vW,
    const float* __restrict__ mub, const float* __restrict__ vb,
    float* __restrict__ out,
    uint32_t wk0, uint32_t wk1, uint32_t bk0, uint32_t bk1)
{
    const int s = blockIdx.x;
    const int t = threadIdx.x;
    __shared__ float Ws[D_OUT * D_H];
    __shared__ float bsm[D_OUT];

#pragma unroll 4
    for (int i = 0; i < (D_OUT * D_H) / 256; i++) {
        int j = t + 256 * i;
        uint32_t e = (uint32_t)(s * (D_OUT * D_H) + j);
        uint2 r = threefry2x32_dev(wk0, wk1, 0u, e);
        Ws[j] = __fmaf_rn(__expf(vW[j]), jax_normal_fast(r.x ^ r.y), muW[j]);
    }
    if (t < D_OUT) {
        uint2 r = threefry2x32_dev(bk0, bk1, 0u, (uint32_t)(s * D_OUT + t));
        bsm[t] = __fmaf_rn(__expf(vb[t]), jax_normal_fast(r.x ^ r.y), mub[t]);
    }
    __syncthreads();

    const int w = t >> 5, l = t & 31;
#pragma unroll
    for (int ri = 0; ri < 8; ri++) {
        int b = w * 8 + ri;
        const float* Hb = H + ((long long)s * BATCH + b) * D_H;
        float h[16];
#pragma unroll
        for (int i = 0; i < 16; i++) h[i] = Hb[l + 32 * i];
#pragma unroll
        for (int o = 0; o < D_OUT; o++) {
            float acc = 0.0f;
#pragma unroll
            for (int i = 0; i < 16; i++)
                acc = __fmaf_rn(h[i], Ws[o * D_H + l + 32 * i], acc);
            acc += __shfl_xor_sync(0xffffffffu, acc, 16);
            acc += __shfl_xor_sync(0xffffffffu, acc, 8);
            acc += __shfl_xor_sync(0xffffffffu, acc, 4);
            acc += __shfl_xor_sync(0xffffffffu, acc, 2);
            acc += __shfl_xor_sync(0xffffffffu, acc, 1);
            if (l == 0) out[((long long)s * BATCH + b) * D_OUT + o] = acc + bsm[o];
        }
    }
}

// ---------------- host-side threefry (subkey derivation) ----------------
static inline uint32_t h_rotl(uint32_t x, int r) { return (x << r) | (x >> (32 - r)); }
static void tf_host(uint32_t k0, uint32_t k1, uint32_t x0, uint32_t x1,
                    uint32_t* o0, uint32_t* o1) {
    uint32_t k2 = k0 ^ k1 ^ 0x1BD11BDAu;
    x0 += k0; x1 += k1;
    static const int R[2][4] = {{13,15,26,6},{17,29,16,24}};
    const uint32_t ks[3] = {k0, k1, k2};
    for (int i = 0; i < 5; i++) {
        for (int r = 0; r < 4; r++) {
            x0 += x1; x1 = h_rotl(x1, R[i & 1][r]); x1 ^= x0;
        }
        x0 += ks[(i + 1) % 3];
        x1 += ks[(i + 2) % 3] + (uint32_t)(i + 1);
    }
    *o0 = x0; *o1 = x1;
}

extern "C" void kernel_launch(void* const* d_in, const int* in_sizes, int n_in,
                              void* d_out, int out_size) {
    const float* x    = (const float*)d_in[0];
    const float* muW0 = (const float*)d_in[1];
    const float* mub0 = (const float*)d_in[2];
    const float* muW1 = (const float*)d_in[3];
    const float* mub1 = (const float*)d_in[4];
    const float* muW2 = (const float*)d_in[5];
    const float* mub2 = (const float*)d_in[6];
    const float* muW3 = (const float*)d_in[7];
    const float* mub3 = (const float*)d_in[8];
    const float* vW0  = (const float*)d_in[9];
    const float* vb0  = (const float*)d_in[10];
    const float* vW1  = (const float*)d_in[11];
    const float* vb1  = (const float*)d_in[12];
    const float* vW2  = (const float*)d_in[13];
    const float* vb2  = (const float*)d_in[14];
    const float* vW3  = (const float*)d_in[15];
    const float* vb3  = (const float*)d_in[16];
    float* out = (float*)d_out;

    uint32_t kk[8][2];
    for (int i = 0; i < 8; i++) tf_host(0u, 1u, 0u, (uint32_t)i, &kk[i][0], &kk[i][1]);

    float *pH1, *pH2, *pH3;
    cudaGetSymbolAddress((void**)&pH1, g_H1);
    cudaGetSymbolAddress((void**)&pH2, g_H2);
    cudaGetSymbolAddress((void**)&pH3, g_H3);

    fused_layer<<<dim3(D_H/64, NSAMP), 256>>>(x,   0,                    muW0, vW0, mub0, vb0,
                                              pH1, D_IN, D_H, 1,
                                              kk[0][0], kk[0][1], kk[1][0], kk[1][1]);
    fused_layer<<<dim3(D_H/64, NSAMP), 256>>>(pH1, (long long)BATCH*D_H, muW1, vW1, mub1, vb1,
                                              pH2, D_H, D_H, 1,
                                              kk[2][0], kk[2][1], kk[3][0], kk[3][1]);
    fused_layer<<<dim3(D_H/64, NSAMP), 256>>>(pH2, (long long)BATCH*D_H, muW2, vW2, mub2, vb2,
                                              pH3, D_H, D_H, 1,
                                              kk[4][0], kk[4][1], kk[5][0], kk[5][1]);
    layer3_fused<<<NSAMP, 256>>>(pH3, muW3, vW3, mub3, vb3, out,
                                 kk[6][0], kk[6][1], kk[7][0], kk[7][1]);
}

// round 5
// speedup vs baseline: 1.1993x; 1.0544x over previous
#include <cuda_runtime.h>
#include <stdint.h>

#define NSAMP 150
#define D_IN  784
#define D_H   512
#define D_OUT 10
#define BATCH 64

// ---------------- device scratch: activations only ----------------
__device__ __align__(16) float g_H1[NSAMP * BATCH * D_H];
__device__ __align__(16) float g_H2[NSAMP * BATCH * D_H];
__device__ __align__(16) float g_H3[NSAMP * BATCH * D_H];

// ---------------- tf32 helpers (3xTF32 error-compensated GEMM) ----------------
__device__ __forceinline__ void tf32_split(float a, uint32_t& hi, uint32_t& lo) {
    asm("cvt.rna.tf32.f32 %0, %1;" : "=r"(hi) : "f"(a));
    float l = a - __uint_as_float(hi);            // exact (hi has <=11-bit mantissa)
    asm("cvt.rna.tf32.f32 %0, %1;" : "=r"(lo) : "f"(l));
}
__device__ __forceinline__ void mma_tf32(float* c,
                                         uint32_t a0, uint32_t a1, uint32_t a2, uint32_t a3,
                                         uint32_t b0, uint32_t b1) {
    asm("mma.sync.aligned.m16n8k8.row.col.f32.tf32.tf32.f32 "
        "{%0,%1,%2,%3}, {%4,%5,%6,%7}, {%8,%9}, {%0,%1,%2,%3};"
        : "+f"(c[0]), "+f"(c[1]), "+f"(c[2]), "+f"(c[3])
        : "r"(a0), "r"(a1), "r"(a2), "r"(a3), "r"(b0), "r"(b1));
}

// ---------------- threefry2x32 (20 rounds), bit-exact vs jax._src.prng ----------------
__device__ __forceinline__ void tf_round(uint32_t& x0, uint32_t& x1, int r) {
    x0 += x1;
    x1 = __funnelshift_l(x1, x1, r);
    x1 ^= x0;
}
__device__ __forceinline__ uint2 threefry2x32_dev(uint32_t k0, uint32_t k1,
                                                  uint32_t x0, uint32_t x1) {
    uint32_t k2 = k0 ^ k1 ^ 0x1BD11BDAu;
    x0 += k0; x1 += k1;
    tf_round(x0,x1,13); tf_round(x0,x1,15); tf_round(x0,x1,26); tf_round(x0,x1,6);
    x0 += k1; x1 += k2 + 1u;
    tf_round(x0,x1,17); tf_round(x0,x1,29); tf_round(x0,x1,16); tf_round(x0,x1,24);
    x0 += k2; x1 += k0 + 2u;
    tf_round(x0,x1,13); tf_round(x0,x1,15); tf_round(x0,x1,26); tf_round(x0,x1,6);
    x0 += k0; x1 += k1 + 3u;
    tf_round(x0,x1,17); tf_round(x0,x1,29); tf_round(x0,x1,16); tf_round(x0,x1,24);
    x0 += k1; x1 += k2 + 4u;
    tf_round(x0,x1,13); tf_round(x0,x1,15); tf_round(x0,x1,26); tf_round(x0,x1,6);
    x0 += k2; x1 += k0 + 5u;
    return make_uint2(x0, x1);
}

// ---------------- bits -> N(0,1): fast-math clone of XLA pipeline ----------------
// NOTE: XLA computes w = y*log(t)/(t-1) with t = 1-y, so t-1 = -y and w == -log(t)
// algebraically; we use -log(t) directly (saves the MUFU rcp + 2 muls).
__device__ __forceinline__ float jax_normal_fast(uint32_t bits) {
    const float LO = -0.99999994039535522461f;
    float f = __uint_as_float((bits >> 9) | 0x3f800000u) - 1.0f;
    float x = fmaxf(__fmaf_rn(f, 2.0f, LO), LO);
    float y = x * x;
    float t = 1.0f - y;
    float w = (t == 1.0f) ? y : -__logf(t);
    float p;
    if (w < 5.0f) {
        float ww = w - 2.5f;
        p =                2.81022636e-08f;
        p = __fmaf_rn(p, ww, 3.43273939e-07f);
        p = __fmaf_rn(p, ww, -3.5233877e-06f);
        p = __fmaf_rn(p, ww, -4.39150654e-06f);
        p = __fmaf_rn(p, ww, 0.00021858087f);
        p = __fmaf_rn(p, ww, -0.00125372503f);
        p = __fmaf_rn(p, ww, -0.00417768164f);
        p = __fmaf_rn(p, ww, 0.246640727f);
        p = __fmaf_rn(p, ww, 1.50140941f);
    } else {
        float ww = __fsqrt_rn(w) - 3.0f;
        p =                -0.000200214257f;
        p = __fmaf_rn(p, ww, 0.000100950558f);
        p = __fmaf_rn(p, ww, 0.00134934322f);
        p = __fmaf_rn(p, ww, -0.00367342844f);
        p = __fmaf_rn(p, ww, 0.00573950773f);
        p = __fmaf_rn(p, ww, -0.0076224613f);
        p = __fmaf_rn(p, ww, 0.00943887047f);
        p = __fmaf_rn(p, ww, 1.00167406f);
        p = __fmaf_rn(p, ww, 2.83297682f);
    }
    return 1.4142135623730951f * (p * x);
}

// ---------------- fused layer: 64x64 tile, double-buffered gen pipeline + tf32 MMA --------
// C[s, 0:64, nblk*64..+64] = relu(A[s] @ W[s]^T + b[s])
__global__ __launch_bounds__(256, 2) void fused_layer(
    const float* __restrict__ A, long long strideA,
    const float* __restrict__ muW, const float* __restrict__ vW,
    const float* __restrict__ mub, const float* __restrict__ vb,
    float* __restrict__ C, int K, int N, int relu,
    uint32_t wk0, uint32_t wk1, uint32_t bk0, uint32_t bk1)
{
    const int s    = blockIdx.y;
    const int nblk = blockIdx.x;
    const int t    = threadIdx.x;      // 256

    __shared__ float As[2][16][68];    // [buf][k][m]
    __shared__ float Bs[2][16][68];    // [buf][k][n]
    __shared__ float bias_s[64];

    const int lr   = t >> 2;           // 0..63 row (A-row / W-row) for producer
    const int lk4  = (t & 3) << 2;     // k offset 0,4,8,12
    const int lane = t & 31;
    const int wrp  = t >> 5;           // 0..7
    const int m0   = (wrp & 3) * 16;   // m-group of this warp
    const int n0b  = (wrp >> 2) * 32;  // n-half of this warp (4 n8-tiles)
    const int ka   = lane & 3;         // k within k8 (fragment)
    const int ra   = lane >> 2;        // row/col within fragment

    const float* Ab     = A + (long long)s * strideA;
    const int    n_glob = nblk * 64 + lr;
    const float* muRow  = muW + (long long)n_glob * K;
    const float* vRow   = vW  + (long long)n_glob * K;
    const uint32_t eBase = ((uint32_t)s * (uint32_t)N + (uint32_t)n_glob) * (uint32_t)K;

    if (t < 64) {
        int nb = nblk * 64 + t;
        uint2 r = threefry2x32_dev(bk0, bk1, 0u, (uint32_t)(s * N + nb));
        bias_s[t] = __fmaf_rn(__expf(vb[nb]), jax_normal_fast(r.x ^ r.y), mub[nb]);
    }

    // ---- prologue: load + gen chunk 0 into registers ----
    float4 av = *(const float4*)(Ab + (long long)lr * K + lk4);
    float4 mv = *(const float4*)(muRow + lk4);
    float4 vv = *(const float4*)(vRow  + lk4);
    float w0, w1, w2, w3;
    {
        uint32_t e0 = eBase + lk4;
        uint2 r0 = threefry2x32_dev(wk0, wk1, 0u, e0 + 0);
        uint2 r1 = threefry2x32_dev(wk0, wk1, 0u, e0 + 1);
        uint2 r2 = threefry2x32_dev(wk0, wk1, 0u, e0 + 2);
        uint2 r3 = threefry2x32_dev(wk0, wk1, 0u, e0 + 3);
        w0 = __fmaf_rn(__expf(vv.x), jax_normal_fast(r0.x ^ r0.y), mv.x);
        w1 = __fmaf_rn(__expf(vv.y), jax_normal_fast(r1.x ^ r1.y), mv.y);
        w2 = __fmaf_rn(__expf(vv.z), jax_normal_fast(r2.x ^ r2.y), mv.z);
        w3 = __fmaf_rn(__expf(vv.w), jax_normal_fast(r3.x ^ r3.y), mv.w);
    }

    float acc[4][4];                   // [n8-tile][c-fragment]
#pragma unroll
    for (int i = 0; i < 4; i++)
#pragma unroll
        for (int j = 0; j < 4; j++) acc[i][j] = 0.0f;

    const int nch = K >> 4;

    // ---- main loop: store(c) | sync | gen(c+1) + MMA(c) ----
    for (int c = 0; c < nch; c++) {
        const int buf = c & 1;
        As[buf][lk4+0][lr] = av.x; As[buf][lk4+1][lr] = av.y;
        As[buf][lk4+2][lr] = av.z; As[buf][lk4+3][lr] = av.w;
        Bs[buf][lk4+0][lr] = w0;   Bs[buf][lk4+1][lr] = w1;
        Bs[buf][lk4+2][lr] = w2;   Bs[buf][lk4+3][lr] = w3;
        __syncthreads();

        if (c + 1 < nch) {
            // load + gen next chunk (ALU/MUFU work; interleaves with MMA below)
            const int k0n = (c + 1) << 4;
            av = *(const float4*)(Ab + (long long)lr * K + k0n + lk4);
            mv = *(const float4*)(muRow + k0n + lk4);
            vv = *(const float4*)(vRow  + k0n + lk4);
            uint32_t e0 = eBase + (uint32_t)(k0n + lk4);
            uint2 r0 = threefry2x32_dev(wk0, wk1, 0u, e0 + 0);
            uint2 r1 = threefry2x32_dev(wk0, wk1, 0u, e0 + 1);
            uint2 r2 = threefry2x32_dev(wk0, wk1, 0u, e0 + 2);
            uint2 r3 = threefry2x32_dev(wk0, wk1, 0u, e0 + 3);
            w0 = __fmaf_rn(__expf(vv.x), jax_normal_fast(r0.x ^ r0.y), mv.x);
            w1 = __fmaf_rn(__expf(vv.y), jax_normal_fast(r1.x ^ r1.y), mv.y);
            w2 = __fmaf_rn(__expf(vv.z), jax_normal_fast(r2.x ^ r2.y), mv.z);
            w3 = __fmaf_rn(__expf(vv.w), jax_normal_fast(r3.x ^ r3.y), mv.w);
        }

        // MMA over chunk c: 2 k8-steps x 4 n8-tiles, 3xTF32
#pragma unroll
        for (int ks = 0; ks < 2; ks++) {
            const int kb = ks * 8;
            float a0f = As[buf][kb + ka    ][m0 + ra    ];
            float a1f = As[buf][kb + ka    ][m0 + ra + 8];
            float a2f = As[buf][kb + ka + 4][m0 + ra    ];
            float a3f = As[buf][kb + ka + 4][m0 + ra + 8];
            uint32_t ah0, al0, ah1, al1, ah2, al2, ah3, al3;
            tf32_split(a0f, ah0, al0); tf32_split(a1f, ah1, al1);
            tf32_split(a2f, ah2, al2); tf32_split(a3f, ah3, al3);
#pragma unroll
            for (int tj = 0; tj < 4; tj++) {
                float b0f = Bs[buf][kb + ka    ][n0b + tj * 8 + ra];
                float b1f = Bs[buf][kb + ka + 4][n0b + tj * 8 + ra];
                uint32_t bh0, bl0, bh1, bl1;
                tf32_split(b0f, bh0, bl0);
                tf32_split(b1f, bh1, bl1);
                mma_tf32(acc[tj], al0, al1, al2, al3, bh0, bh1);  // alo*bhi
                mma_tf32(acc[tj], ah0, ah1, ah2, ah3, bl0, bl1);  // ahi*blo
                mma_tf32(acc[tj], ah0, ah1, ah2, ah3, bh0, bh1);  // ahi*bhi
            }
        }
        __syncthreads();
    }

    // ---- epilogue: fragment layout -> gmem, +bias, relu ----
    const int row0 = m0 + ra;
    const int row1 = m0 + ra + 8;
#pragma unroll
    for (int tj = 0; tj < 4; tj++) {
        int n = n0b + tj * 8 + 2 * ka;              // 2 adjacent cols per lane
        float bb0 = bias_s[n], bb1 = bias_s[n + 1];
        float v00 = acc[tj][0] + bb0, v01 = acc[tj][1] + bb1;
        float v10 = acc[tj][2] + bb0, v11 = acc[tj][3] + bb1;
        if (relu) {
            v00 = fmaxf(v00, 0.f); v01 = fmaxf(v01, 0.f);
            v10 = fmaxf(v10, 0.f); v11 = fmaxf(v11, 0.f);
        }
        float* p0 = C + ((long long)s * 64 + row0) * N + nblk * 64 + n;
        float* p1 = C + ((long long)s * 64 + row1) * N + nblk * 64 + n;
        *(float2*)p0 = make_float2(v00, v01);
        *(float2*)p1 = make_float2(v10, v11);
    }
}

// ---------------- final layer: 2 blocks per sample, gen partitioned by output-half --------
__global__ __launch_bounds__(256) void layer3_fused(
    const float* __restrict__ H,
    const float* __restrict__ muW, const float* __restrict__ vW,
    const float* __restrict__ mub, const float* __restrict__ vb,
    float* __restrict__ out,
    uint32_t wk0, uint32_t wk1, uint32_t bk0, uint32_t bk1)
{
    const int s = blockIdx.x;
    const int h = blockIdx.y;          // output half: o in [5h, 5h+5)
    const int t = threadIdx.x;
    __shared__ float Ws[5 * D_H];
    __shared__ float bsm[5];

#pragma unroll
    for (int i = 0; i < (5 * D_H) / 256; i++) {     // 10 iters
        int j = t + 256 * i;
        uint32_t e = (uint32_t)(s * (D_OUT * D_H) + h * (5 * D_H) + j);
        uint2 r = threefry2x32_dev(wk0, wk1, 0u, e);
        int jg = h * (5 * D_H) + j;
        Ws[j] = __fmaf_rn(__expf(vW[jg]), jax_normal_fast(r.x ^ r.y), muW[jg]);
    }
    if (t < 5) {
        int og = h * 5 + t;
        uint2 r = threefry2x32_dev(bk0, bk1, 0u, (uint32_t)(s * D_OUT + og));
        bsm[t] = __fmaf_rn(__expf(vb[og]), jax_normal_fast(r.x ^ r.y), mub[og]);
    }
    __syncthreads();

    const int w = t >> 5, l = t & 31;
#pragma unroll
    for (int ri = 0; ri < 8; ri++) {
        int b = w * 8 + ri;
        const float* Hb = H + ((long long)s * BATCH + b) * D_H;
        float hh[16];
#pragma unroll
        for (int i = 0; i < 16; i++) hh[i] = Hb[l + 32 * i];
#pragma unroll
        for (int o = 0; o < 5; o++) {
            float acc = 0.0f;
#pragma unroll
            for (int i = 0; i < 16; i++)
                acc = __fmaf_rn(hh[i], Ws[o * D_H + l + 32 * i], acc);
            acc += __shfl_xor_sync(0xffffffffu, acc, 16);
            acc += __shfl_xor_sync(0xffffffffu, acc, 8);
            acc += __shfl_xor_sync(0xffffffffu, acc, 4);
            acc += __shfl_xor_sync(0xffffffffu, acc, 2);
            acc += __shfl_xor_sync(0xffffffffu, acc, 1);
            if (l == 0)
                out[((long long)s * BATCH + b) * D_OUT + h * 5 + o] = acc + bsm[o];
        }
    }
}

// ---------------- host-side threefry (subkey derivation) ----------------
static inline uint32_t h_rotl(uint32_t x, int r) { return (x << r) | (x >> (32 - r)); }
static void tf_host(uint32_t k0, uint32_t k1, uint32_t x0, uint32_t x1,
                    uint32_t* o0, uint32_t* o1) {
    uint32_t k2 = k0 ^ k1 ^ 0x1BD11BDAu;
    x0 += k0; x1 += k1;
    static const int R[2][4] = {{13,15,26,6},{17,29,16,24}};
    const uint32_t ks[3] = {k0, k1, k2};
    for (int i = 0; i < 5; i++) {
        for (int r = 0; r < 4; r++) {
            x0 += x1; x1 = h_rotl(x1, R[i & 1][r]); x1 ^= x0;
        }
        x0 += ks[(i + 1) % 3];
        x1 += ks[(i + 2) % 3] + (uint32_t)(i + 1);
    }
    *o0 = x0; *o1 = x1;
}

extern "C" void kernel_launch(void* const* d_in, const int* in_sizes, int n_in,
                              void* d_out, int out_size) {
    const float* x    = (const float*)d_in[0];
    const float* muW0 = (const float*)d_in[1];
    const float* mub0 = (const float*)d_in[2];
    const float* muW1 = (const float*)d_in[3];
    const float* mub1 = (const float*)d_in[4];
    const float* muW2 = (const float*)d_in[5];
    const float* mub2 = (const float*)d_in[6];
    const float* muW3 = (const float*)d_in[7];
    const float* mub3 = (const float*)d_in[8];
    const float* vW0  = (const float*)d_in[9];
    const float* vb0  = (const float*)d_in[10];
    const float* vW1  = (const float*)d_in[11];
    const float* vb1  = (const float*)d_in[12];
    const float* vW2  = (const float*)d_in[13];
    const float* vb2  = (const float*)d_in[14];
    const float* vW3  = (const float*)d_in[15];
    const float* vb3  = (const float*)d_in[16];
    float* out = (float*)d_out;

    uint32_t kk[8][2];
    for (int i = 0; i < 8; i++) tf_host(0u, 1u, 0u, (uint32_t)i, &kk[i][0], &kk[i][1]);

    float *pH1, *pH2, *pH3;
    cudaGetSymbolAddress((void**)&pH1, g_H1);
    cudaGetSymbolAddress((void**)&pH2, g_H2);
    cudaGetSymbolAddress((void**)&pH3, g_H3);

    fused_layer<<<dim3(D_H/64, NSAMP), 256>>>(x,   0,                    muW0, vW0, mub0, vb0,
                                              pH1, D_IN, D_H, 1,
                                              kk[0][0], kk[0][1], kk[1][0], kk[1][1]);
    fused_layer<<<dim3(D_H/64, NSAMP), 256>>>(pH1, (long long)BATCH*D_H, muW1, vW1, mub1, vb1,
                                              pH2, D_H, D_H, 1,
                                              kk[2][0], kk[2][1], kk[3][0], kk[3][1]);
    fused_layer<<<dim3(D_H/64, NSAMP), 256>>>(pH2, (long long)BATCH*D_H, muW2, vW2, mub2, vb2,
                                              pH3, D_H, D_H, 1,
                                              kk[4][0], kk[4][1], kk[5][0], kk[5][1]);
    layer3_fused<<<dim3(NSAMP, 2), 256>>>(pH3, muW3, vW3, mub3, vb3, out,
                                          kk[6][0], kk[6][1], kk[7][0], kk[7][1]);
}